// round 15
// baseline (speedup 1.0000x reference)
#include <cuda_runtime.h>
#include <cuda_fp16.h>
#include <math.h>
#include <stdint.h>

// ---------------- problem constants ----------------
#define NB   16
#define CIN  512
#define COUT 512
#define HH   64
#define WW   64
#define HW   (HH*WW)
#define STY  512
#define KT   9
#define XP   4356          // padded pixels per sample: 66*66

// ---------------- scratch (device globals) ----------------
__device__ float g_s[NB*CIN];
__device__ float g_wsq[COUT*CIN];
__device__ float g_demod[NB*COUT];
// modulated x, fp16, transposed+padded: [n][P=(h+1)*66+(w+1)][ci]
__device__ __half g_xh[(size_t)NB*XP*CIN];
// weights fp16, transposed: [tap][co][ci]
__device__ __half g_wh[(size_t)KT*COUT*CIN];

// ---------------- PTX helpers ----------------
__device__ __forceinline__ uint32_t smem_u32(const void* p) {
    uint32_t a;
    asm("{ .reg .u64 t; cvta.to.shared.u64 t, %1; cvt.u32.u64 %0, t; }"
        : "=r"(a) : "l"(p));
    return a;
}
__device__ __forceinline__ void cp16(uint32_t dst, const void* src) {
    asm volatile("cp.async.cg.shared.global [%0], [%1], 16;"
                 :: "r"(dst), "l"(src) : "memory");
}
#define CP_COMMIT() asm volatile("cp.async.commit_group;" ::: "memory")
#define CP_WAIT2()  asm volatile("cp.async.wait_group 2;" ::: "memory")
#define CP_WAIT0()  asm volatile("cp.async.wait_group 0;" ::: "memory")

__device__ __forceinline__ void ldm_x4(uint32_t* r, uint32_t addr) {
    asm volatile("ldmatrix.sync.aligned.m8n8.x4.shared.b16 {%0,%1,%2,%3}, [%4];"
        : "=r"(r[0]), "=r"(r[1]), "=r"(r[2]), "=r"(r[3]) : "r"(addr));
}
__device__ __forceinline__ void mma16816(float* c, const uint32_t* a, const uint32_t* b) {
    asm volatile(
        "mma.sync.aligned.m16n8k16.row.col.f32.f16.f16.f32 "
        "{%0,%1,%2,%3}, {%4,%5,%6,%7}, {%8,%9}, {%0,%1,%2,%3};"
        : "+f"(c[0]), "+f"(c[1]), "+f"(c[2]), "+f"(c[3])
        : "r"(a[0]), "r"(a[1]), "r"(a[2]), "r"(a[3]), "r"(b[0]), "r"(b[1]));
}

// ---------------- prologue kernels ----------------
__global__ void k_style(const float* __restrict__ style,
                        const float* __restrict__ style_w,
                        const float* __restrict__ style_b)
{
    int idx = blockIdx.x * blockDim.x + threadIdx.x;
    if (idx >= NB*CIN) return;
    int n = idx >> 9, ci = idx & 511;
    const float* st = style + n * STY;
    const float* sw = style_w + ci * STY;
    float acc = 0.f;
    #pragma unroll 8
    for (int k = 0; k < STY; ++k) acc += st[k] * sw[k];
    g_s[idx] = acc + style_b[ci];
}

// wsq + fp16 weight transpose to [tap][co][ci]
__global__ void k_wprep(const float* __restrict__ weight)
{
    int idx = blockIdx.x * blockDim.x + threadIdx.x;   // COUT*CIN
    if (idx >= COUT*CIN) return;
    int co = idx >> 9, ci = idx & 511;
    const float* w = weight + (size_t)idx * KT;
    float acc = 0.f;
    #pragma unroll
    for (int tap = 0; tap < KT; ++tap) {
        float v = w[tap];
        acc += v * v;
        g_wh[((size_t)tap * COUT + co) * CIN + ci] = __float2half(v);
    }
    g_wsq[idx] = acc;
}

__global__ void k_demod()
{
    int idx = blockIdx.x * blockDim.x + threadIdx.x;
    if (idx >= NB*COUT) return;
    int n = idx >> 9, co = idx & 511;
    const float* sp = g_s + n * CIN;
    const float* wq = g_wsq + co * CIN;
    float acc = 0.f;
    #pragma unroll 8
    for (int ci = 0; ci < CIN; ++ci) { float sv = sp[ci]; acc += sv * sv * wq[ci]; }
    g_demod[idx] = rsqrtf(acc + 1e-8f);
}

// zero only the 260 border pixel-rows per sample
__global__ void k_xzero_border()
{
    int idx = blockIdx.x * blockDim.x + threadIdx.x;
    if (idx >= NB*260*64) return;
    int cv = idx & 63;
    int b  = (idx >> 6) % 260;
    int n  = idx / (260*64);
    int P;
    if (b < 66)       P = b;                       // top row
    else if (b < 132) P = 65*66 + (b - 66);        // bottom row
    else if (b < 196) P = (b - 132 + 1)*66;        // left col (rows 1..64)
    else              P = (b - 196 + 1)*66 + 65;   // right col
    size_t o = (((size_t)n * XP + P) * CIN) + cv*8;
    *(uint4*)(g_xh + o) = make_uint4(0,0,0,0);
}

// modulate + fp16 + transpose to [P][ci]
__global__ void k_xprep(const float* __restrict__ x)
{
    __shared__ float s[32][33];
    int p0  = blockIdx.x * 32;
    int ci0 = blockIdx.y * 32;
    int n   = blockIdx.z;
    int tx = threadIdx.x, ty = threadIdx.y;   // 32 x 8

    #pragma unroll
    for (int k = 0; k < 4; ++k) {
        int ci = ci0 + ty + k*8;
        float v = x[((size_t)(n*CIN + ci)) * HW + p0 + tx] * g_s[n*CIN + ci];
        s[tx][ty + k*8] = v;
    }
    __syncthreads();
    #pragma unroll
    for (int k = 0; k < 4; ++k) {
        int pl = ty + k*8;
        int p  = p0 + pl;
        int h  = p >> 6, w = p & 63;
        size_t P = (size_t)(h + 1) * 66 + (w + 1);
        size_t o = ((size_t)n * XP + P) * CIN + ci0 + tx;
        g_xh[o] = __float2half(s[pl][tx]);
    }
}

// ---------------- main MMA conv ----------------
// smem: X double buffer 2x8448, A ring 4x4096.
// A prefetch distance 3; one commit group per stage (empty at tail) so the
// wait discipline is a uniform wait_group 2; ONE barrier per stage; the
// 9-tap loop is fully unrolled so kh/kw/slots/prefetch indices are constants.
#define XBUF 8448
#define ABUF 4096
#define SM_X 0
#define SM_A (2*XBUF)                  // 16896
#define SMEM_BYTES (2*XBUF + 4*ABUF)   // 33280

__global__ void __launch_bounds__(256) k_conv_mma(
    const float* __restrict__ noise,
    const float* __restrict__ noise_w,
    float* __restrict__ out)
{
    __shared__ __align__(128) char smem[SMEM_BYTES];
    const uint32_t sb = smem_u32(smem);
    const uint32_t sbX = sb + SM_X;
    const uint32_t sbA = sb + SM_A;

    const int tid = threadIdx.x;
    const int lane = tid & 31, wid = tid >> 5;
    const int warp_m = wid >> 2;          // 0..1  (64 co)
    const int warp_n = wid & 3;           // 0..3  (32 px)

    const int pb  = blockIdx.x;           // 32 pixel blocks (128 px = 2 rows)
    const int co0 = blockIdx.y << 7;
    const int n   = blockIdx.z;
    const int p0  = pb << 7;
    const int h0  = pb << 1;              // padded rows h0..h0+3 needed

    // A staging coords
    const int arow = tid >> 1;
    const int aseg = tid & 1;

    // A fragment address components
    const uint32_t a_row = warp_m*64 + (lane & 7) + ((lane >> 3) & 1) * 8;
    const uint32_t a_col = ((lane >> 4) & 1) * 16;

    // B per-lane fixed pixel offsets (two jp halves)
    uint32_t pixoff[2];
    {
        int khalf = (lane >> 3) & 1;
        #pragma unroll
        for (int jp = 0; jp < 2; ++jp) {
            int px = warp_n*32 + (lane & 7) + ((lane >> 4) & 1)*8 + jp*16;
            int dt = px >> 6, col = px & 63;
            pixoff[jp] = (uint32_t)(dt*66 + col)*32 + khalf*16;
        }
    }

    float acc[4][4][4];
    #pragma unroll
    for (int mt = 0; mt < 4; ++mt)
        #pragma unroll
        for (int nt = 0; nt < 4; ++nt)
            #pragma unroll
            for (int q = 0; q < 4; ++q) acc[mt][nt][q] = 0.f;

    // stage X for chunk ck into buffer ck&1 (264 rows x 32B)
    #define STAGE_X(ck) do {                                                 \
        int ciN = (ck) << 4;                                                 \
        uint32_t xd = sbX + ((ck) & 1) * XBUF;                               \
        for (int i = tid; i < 528; i += 256) {                               \
            int row = i >> 1, seg = i & 1;                                   \
            int pr  = row / 66, pc = row - pr*66;                            \
            size_t so = ((size_t)n*XP + (size_t)(h0 + pr)*66 + pc)*CIN + ciN + seg*8; \
            cp16(xd + row*32 + seg*16, g_xh + so);                           \
        }                                                                    \
    } while (0)
    // stage A for chunk ckA, tap tapA into ring slot 'slot'
    #define STAGE_A_CT(ckA, tapA, slot) do {                                 \
        size_t ao = ((size_t)((tapA)*COUT + co0 + arow))*CIN + ((ckA) << 4) + aseg*8; \
        cp16(sbA + (slot)*ABUF + arow*32 + aseg*16, g_wh + ao);              \
    } while (0)

    // prologue: groups {X(0), A(0)}, {A(1)}, {A(2)}  (stage s ring slot = (ck+tap)&3)
    STAGE_X(0);
    STAGE_A_CT(0, 0, 0);
    CP_COMMIT();
    STAGE_A_CT(0, 1, 1);
    CP_COMMIT();
    STAGE_A_CT(0, 2, 2);
    CP_COMMIT();

    #pragma unroll 1
    for (int ck = 0; ck < 32; ++ck) {
        const int ckm4 = ck & 3;
        #pragma unroll
        for (int tap = 0; tap < KT; ++tap) {
            // ring slot of stage s = ck*9+tap is (ck+tap)&3 (9 mod 4 == 1)
            CP_WAIT2();
            __syncthreads();

            // prefetch A for stage s+3 (constants after unroll), X at tap==0
            {
                const int tapA = (tap + 3 < 9) ? tap + 3 : tap - 6;
                const int ckA  = (tap + 3 < 9) ? ck : ck + 1;
                if (tap < 6 || ck < 31)
                    STAGE_A_CT(ckA, tapA, (ckm4 + tap + 3) & 3);
            }
            if (tap == 0 && ck < 31) STAGE_X(ck + 1);
            CP_COMMIT();

            // ---- fragments ----
            const uint32_t ab = sbA + ((ckm4 + tap) & 3)*ABUF;
            uint32_t a[4][4];
            #pragma unroll
            for (int mt = 0; mt < 4; ++mt)
                ldm_x4(a[mt], ab + (a_row + mt*16)*32 + a_col);

            const int kh = tap / 3;           // constant after unroll
            const int kw = tap - kh*3;        // constant after unroll
            const uint32_t xb = sbX + (ck & 1)*XBUF + (uint32_t)(kh*66 + kw)*32;
            uint32_t bh[2][4];
            #pragma unroll
            for (int jp = 0; jp < 2; ++jp)
                ldm_x4(bh[jp], xb + pixoff[jp]);

            // ---- mma ----
            #pragma unroll
            for (int mt = 0; mt < 4; ++mt)
                #pragma unroll
                for (int nt = 0; nt < 4; ++nt)
                    mma16816(acc[mt][nt], a[mt], &bh[nt >> 1][(nt & 1)*2]);
        }
    }
    CP_WAIT0();

    // ---- epilogue: demod + noise + LeakyReLU ----
    const float nw = noise_w[0];
    const int g  = lane >> 2;
    const int tg = lane & 3;
    #pragma unroll
    for (int mt = 0; mt < 4; ++mt) {
        int co = co0 + warp_m*64 + mt*16 + g;
        float d0 = g_demod[(n << 9) + co];
        float d1 = g_demod[(n << 9) + co + 8];
        #pragma unroll
        for (int nt = 0; nt < 4; ++nt) {
            int px = p0 + warp_n*32 + nt*8 + tg*2;
            float nz0 = nw * noise[(size_t)n*HW + px];
            float nz1 = nw * noise[(size_t)n*HW + px + 1];
            float v0 = acc[mt][nt][0] * d0 + nz0;
            float v1 = acc[mt][nt][1] * d0 + nz1;
            float v2 = acc[mt][nt][2] * d1 + nz0;
            float v3 = acc[mt][nt][3] * d1 + nz1;
            v0 = (v0 >= 0.f) ? v0 : 0.2f*v0;
            v1 = (v1 >= 0.f) ? v1 : 0.2f*v1;
            v2 = (v2 >= 0.f) ? v2 : 0.2f*v2;
            v3 = (v3 >= 0.f) ? v3 : 0.2f*v3;
            *(float2*)(out + (((size_t)n*COUT + co    ) << 12) + px) = make_float2(v0, v1);
            *(float2*)(out + (((size_t)n*COUT + co + 8) << 12) + px) = make_float2(v2, v3);
        }
    }
}

// ---------------- launcher ----------------
extern "C" void kernel_launch(void* const* d_in, const int* in_sizes, int n_in,
                              void* d_out, int out_size)
{
    const float* x       = (const float*)d_in[0];
    const float* style   = (const float*)d_in[1];
    const float* noise   = (const float*)d_in[2];
    const float* weight  = (const float*)d_in[3];
    const float* style_w = (const float*)d_in[4];
    const float* style_b = (const float*)d_in[5];
    const float* noise_w = (const float*)d_in[6];
    float* out           = (float*)d_out;

    k_style<<<(NB*CIN + 255)/256, 256>>>(style, style_w, style_b);
    k_wprep<<<(COUT*CIN + 255)/256, 256>>>(weight);
    k_demod<<<(NB*COUT + 255)/256, 256>>>();
    k_xzero_border<<<(NB*260*64 + 255)/256, 256>>>();
    {
        dim3 grid(HW/32, CIN/32, NB);
        dim3 block(32, 8);
        k_xprep<<<grid, block>>>(x);
    }
    {
        dim3 grid(HW/128, COUT/128, NB);   // 32 x 4 x 16 = 2048 blocks
        k_conv_mma<<<grid, 256>>>(noise, noise_w, out);
    }
}